// round 12
// baseline (speedup 1.0000x reference)
#include <cuda_runtime.h>
#include <cuda_bf16.h>
#include <math.h>

typedef unsigned long long u64;

#define N_OSC 50
#define N_PER 40
#define STEPS 100
#define BATCH 8192
#define NPAIR 25   // oscillator pairs; units = 25 ops x 128 bg64 = 3200 warps

// ---------------- packed f32x2 helpers ----------------
#define FMA2(d, a, b, c) \
    asm("fma.rn.f32x2 %0, %1, %2, %3;" : "=l"(d) : "l"(a), "l"(b), "l"(c))
#define PACK2(v, lo, hi) \
    asm("mov.b64 %0, {%1, %2};" : "=l"(v) : "f"(lo), "f"(hi))
#define UNPACK2(lo, hi, v) \
    asm("mov.b64 {%0, %1}, %2;" : "=f"(lo), "=f"(hi) : "l"(v))
// out-of-place relu (used in MLP where value is also needed elsewhere)
#define RELU2(d, s)                      \
    do {                                 \
        float _lo, _hi;                  \
        UNPACK2(_lo, _hi, s);            \
        _lo = fmaxf(_lo, 0.f);           \
        _hi = fmaxf(_hi, 0.f);           \
        PACK2(d, _lo, _hi);              \
    } while (0)
// IN-PLACE packed relu: "+l" keeps src/dst the same u64 so ptxas can
// apply FMNMX to the register pair's halves with NO pack/unpack MOVs.
#define RELU2IP(v)                                                        \
    asm("{ .reg .f32 _lo, _hi;\n\t"                                       \
        "mov.b64 {_lo,_hi}, %0;\n\t"                                      \
        "max.f32 _lo, _lo, 0f00000000;\n\t"                               \
        "max.f32 _hi, _hi, 0f00000000;\n\t"                               \
        "mov.b64 %0, {_lo,_hi}; }"                                        \
        : "+l"(v))

// ---------------- device scratch (no allocs allowed) ----------------
__device__ float g_x3[BATCH * 100];            // o0 initial states, [b][100]
__device__ float g_direct[BATCH];              // direct torque (incl fcd_b)
__device__ float g_cpack[NPAIR * N_PER * 12];  // packed per-(osc-pair, n) consts
__device__ float2 g_fc2p[128 * 128];           // fc2_w k-major, duplicated pairs
__device__ float2 g_fc3p[128 * 128];           // fc3_w k-major, dup, zero-padded
__device__ float g_tqp[NPAIR * STEPS * BATCH]; // per-osc-pair torque partials

// ============================================================
// K0 (pos 1): prep_mlp — duplicated-pair k-major weight tables
// ============================================================
__global__ void prep_mlp_kernel(const float* __restrict__ fc2_w,
                                const float* __restrict__ fc3_w) {
    int i = blockIdx.x * blockDim.x + threadIdx.x;  // < 16384
    int k = i / 128, j = i % 128;
    float w2 = fc2_w[j * 128 + k];
    g_fc2p[i] = make_float2(w2, w2);
    float w3 = (j < 100) ? fc3_w[j * 128 + k] : 0.f;
    g_fc3p[i] = make_float2(w3, w3);
}

// ============================================================
// K1 (pos 2): MLP v3. Block = 256 threads = 16 batch rows.
// ============================================================
__global__ __launch_bounds__(256) void mlp_kernel(
    const float* __restrict__ x,
    const float* __restrict__ fc1_w, const float* __restrict__ fc1_b,
    const float* __restrict__ fc2_b, const float* __restrict__ fc3_b,
    const float* __restrict__ fcd_w, const float* __restrict__ fcd_b) {
    __shared__ u64 s_h[128 * 8];   // [hidden k][row-pair p]
    __shared__ u64 s_h2[128 * 8];

    const int tid = threadIdx.x;
    const int j = tid & 127;
    const int rg = tid >> 7;
    const int base = blockIdx.x * 16;
    const int r0 = base + 8 * rg;

    u64 x0p[4], x1p[4];
#pragma unroll
    for (int p = 0; p < 4; ++p) {
        float2 ra = ((const float2*)x)[r0 + 2 * p];
        float2 rb = ((const float2*)x)[r0 + 2 * p + 1];
        PACK2(x0p[p], ra.x, rb.x);
        PACK2(x1p[p], ra.y, rb.y);
    }
    {
        float w0 = fc1_w[j * 2 + 0], w1 = fc1_w[j * 2 + 1], b1v = fc1_b[j];
        u64 w02, w12, b12;
        PACK2(w02, w0, w0);
        PACK2(w12, w1, w1);
        PACK2(b12, b1v, b1v);
#pragma unroll
        for (int p = 0; p < 4; ++p) {
            u64 t;
            FMA2(t, w02, x0p[p], b12);
            FMA2(t, w12, x1p[p], t);
            RELU2IP(t);
            s_h[j * 8 + 4 * rg + p] = t;
        }
    }
    __syncthreads();

    if (tid < 16) {
        const float* shf = (const float*)s_h;
        float acc = 0.f;
#pragma unroll 8
        for (int k = 0; k < 128; ++k) acc = fmaf(shf[k * 16 + tid], fcd_w[k], acc);
        g_direct[base + tid] = acc + fcd_b[0];
    }

    u64 a0, a1, a2, a3;
    {
        float bb = fc2_b[j];
        PACK2(a0, bb, bb);
        a1 = a0; a2 = a0; a3 = a0;
    }
    const u64* w2p = (const u64*)g_fc2p;
#pragma unroll 8
    for (int k = 0; k < 128; ++k) {
        u64 wp = __ldg(w2p + k * 128 + j);
        const u64* hh = s_h + k * 8 + 4 * rg;
        FMA2(a0, wp, hh[0], a0);
        FMA2(a1, wp, hh[1], a1);
        FMA2(a2, wp, hh[2], a2);
        FMA2(a3, wp, hh[3], a3);
    }
    RELU2IP(a0); RELU2IP(a1); RELU2IP(a2); RELU2IP(a3);
    s_h2[j * 8 + 4 * rg + 0] = a0;
    s_h2[j * 8 + 4 * rg + 1] = a1;
    s_h2[j * 8 + 4 * rg + 2] = a2;
    s_h2[j * 8 + 4 * rg + 3] = a3;
    __syncthreads();

    u64 c0, c1, c2, c3;
    {
        float bb = (j < 100) ? fc3_b[j] : 0.f;
        PACK2(c0, bb, bb);
        c1 = c0; c2 = c0; c3 = c0;
    }
    const u64* w3p = (const u64*)g_fc3p;
#pragma unroll 8
    for (int k = 0; k < 128; ++k) {
        u64 wp = __ldg(w3p + k * 128 + j);
        const u64* hh = s_h2 + k * 8 + 4 * rg;
        FMA2(c0, wp, hh[0], c0);
        FMA2(c1, wp, hh[1], c1);
        FMA2(c2, wp, hh[2], c2);
        FMA2(c3, wp, hh[3], c3);
    }
    if (j < 100) {
        float lo, hi;
        UNPACK2(lo, hi, c0);
        g_x3[(size_t)(r0 + 0) * 100 + j] = lo;
        g_x3[(size_t)(r0 + 1) * 100 + j] = hi;
        UNPACK2(lo, hi, c1);
        g_x3[(size_t)(r0 + 2) * 100 + j] = lo;
        g_x3[(size_t)(r0 + 3) * 100 + j] = hi;
        UNPACK2(lo, hi, c2);
        g_x3[(size_t)(r0 + 4) * 100 + j] = lo;
        g_x3[(size_t)(r0 + 5) * 100 + j] = hi;
        UNPACK2(lo, hi, c3);
        g_x3[(size_t)(r0 + 6) * 100 + j] = lo;
        g_x3[(size_t)(r0 + 7) * 100 + j] = hi;
    }
}

// ============================================================
// K2 (pos 3): prep_osc — pack oscillator constants
// ============================================================
__global__ void prep_osc_kernel(const float* __restrict__ enc,
                                const float* __restrict__ obias,
                                const float* __restrict__ dec,
                                const float* __restrict__ fc4_w) {
    int i = blockIdx.x * blockDim.x + threadIdx.x;
    if (i < NPAIR * N_PER) {
        int op = i / N_PER, n = i % N_PER;
        int oA = 2 * op, oB = 2 * op + 1;
        float* dst = g_cpack + (size_t)i * 12;
        dst[0]  = enc[oA * 80 + n * 2 + 0];
        dst[1]  = enc[oB * 80 + n * 2 + 0];
        dst[2]  = enc[oA * 80 + n * 2 + 1];
        dst[3]  = enc[oB * 80 + n * 2 + 1];
        dst[4]  = obias[oA * 40 + n];
        dst[5]  = obias[oB * 40 + n];
        dst[6]  = dec[oA * 80 + n];
        dst[7]  = dec[oB * 80 + n];
        dst[8]  = dec[oA * 80 + 40 + n];
        dst[9]  = dec[oB * 80 + 40 + n];
        dst[10] = fc4_w[oA * 40 + n];
        dst[11] = fc4_w[oB * 40 + n];
    }
}

// ============================================================
// K3 (pos 4): oscillator scan v8 — 2-elem/thread (3200 warps, the
// best-measured issue efficiency), pad-slot prefetch (no wrap ALU),
// and IN-PLACE packed relu so the FMNMXs hit the FMA2 destination
// pair directly — removing the pack/unpack MOVs that R11's profile
// showed were padding issue up to exactly the fma demand.
// Mix per n: 10 FMA2 (20 fma-cyc) + 4 FMNMX + 3 LDS ≈ 18 issues.
// ============================================================
__global__ __launch_bounds__(256, 4) void osc_kernel() {
    __shared__ float4 s_c[123];  // 40 n x 3 float4 + 3 pad (prefetch overrun)
    const unsigned op = blockIdx.x % NPAIR;
    if (threadIdx.x < 120)
        s_c[threadIdx.x] = ((const float4*)g_cpack)[op * 120 + threadIdx.x];
    __syncthreads();

    const int lane = threadIdx.x & 31;
    const int wrp = threadIdx.x >> 5;
    const unsigned bg = (blockIdx.x / NPAIR) * 8 + wrp;  // 128 groups of 64
    const int b0 = bg * 64 + lane;
    const int b1 = b0 + 32;

    u64 dt2;
    PACK2(dt2, 0.01f, 0.01f);

    float4 oA = __ldg((const float4*)(g_x3 + (size_t)b0 * 100 + op * 4));
    float4 oB = __ldg((const float4*)(g_x3 + (size_t)b1 * 100 + op * 4));
    u64 oxa, oya, oxb, oyb;
    PACK2(oxa, oA.x, oA.z);
    PACK2(oya, oA.y, oA.w);
    PACK2(oxb, oB.x, oB.z);
    PACK2(oyb, oB.y, oB.w);

    const ulonglong2* cp = (const ulonglong2*)s_c;
    float* tq_out = g_tqp + (size_t)op * (STEPS * BATCH) + b0;

    for (int t = 0; t < STEPS; ++t) {
        ulonglong2 p0 = cp[0], p1 = cp[1], p2 = cp[2];
        u64 dxa = 0ull, dya = 0ull, tqa = 0ull;
        u64 dxb = 0ull, dyb = 0ull, tqb = 0ull;
#pragma unroll 8
        for (int n = 0; n < N_PER; ++n) {
            ulonglong2 c0 = p0, c1 = p1, c2 = p2;
            p0 = cp[n * 3 + 3];   // n=39 reads pad, discarded
            p1 = cp[n * 3 + 4];
            p2 = cp[n * 3 + 5];

            u64 ta, tb;
            FMA2(ta, oxa, c0.x, c1.x);
            FMA2(tb, oxb, c0.x, c1.x);
            FMA2(ta, oya, c0.y, ta);
            FMA2(tb, oyb, c0.y, tb);
            RELU2IP(ta);
            RELU2IP(tb);
            FMA2(dxa, c1.y, ta, dxa);
            FMA2(dxb, c1.y, tb, dxb);
            FMA2(dya, c2.x, ta, dya);
            FMA2(dyb, c2.x, tb, dyb);
            FMA2(tqa, c2.y, ta, tqa);
            FMA2(tqb, c2.y, tb, tqb);
        }
        FMA2(oxa, dt2, dxa, oxa);
        FMA2(oya, dt2, dya, oya);
        FMA2(oxb, dt2, dxb, oxb);
        FMA2(oyb, dt2, dyb, oyb);
        float sl, sh;
        UNPACK2(sl, sh, tqa);
        float s0 = sl + sh;
        UNPACK2(sl, sh, tqb);
        float s1 = sl + sh;
        tq_out[t * BATCH]      = s0;
        tq_out[t * BATCH + 32] = s1;
    }
}

// ============================================================
// K4 (pos 5): fused reduce + dir + pendulum scan + outputs
// ============================================================
__global__ void scan_kernel(const float* __restrict__ x,
                            const float* __restrict__ fc4_b,
                            float* __restrict__ out) {
    int b = blockIdx.x * blockDim.x + threadIdx.x;  // < BATCH
    float theta = x[b * 2 + 0];
    float omega = 0.f;
    const float dir = g_direct[b] + fc4_b[0];
    float2* outL = (float2*)out;
    float* outT = out + STEPS * BATCH * 2;
    for (int t = 0; t < STEPS; ++t) {
        float s = 0.f;
        const float* p = g_tqp + (size_t)t * BATCH + b;
#pragma unroll
        for (int q = 0; q < NPAIR; ++q) s += p[(size_t)q * (STEPS * BATCH)];
        float tau = s + dir;
        float alpha = tau - sinf(theta) - 0.1f * omega;
        float th2 = theta + 0.01f * omega;
        float om2 = omega + 0.01f * alpha;
        outL[t * BATCH + b] = make_float2(th2, om2);
        outT[t * BATCH + b] = tau;
        theta = th2;
        omega = om2;
    }
}

// ============================================================
extern "C" void kernel_launch(void* const* d_in, const int* in_sizes, int n_in,
                              void* d_out, int out_size) {
    const float* x     = (const float*)d_in[0];
    const float* fc1_w = (const float*)d_in[1];
    const float* fc1_b = (const float*)d_in[2];
    const float* fc2_w = (const float*)d_in[3];
    const float* fc2_b = (const float*)d_in[4];
    const float* fc3_w = (const float*)d_in[5];
    const float* fc3_b = (const float*)d_in[6];
    const float* fcd_w = (const float*)d_in[7];
    const float* fcd_b = (const float*)d_in[8];
    const float* enc   = (const float*)d_in[9];
    const float* obias = (const float*)d_in[10];
    const float* dec   = (const float*)d_in[11];
    const float* fc4_w = (const float*)d_in[12];
    const float* fc4_b = (const float*)d_in[13];
    float* out = (float*)d_out;

    prep_mlp_kernel<<<64, 256>>>(fc2_w, fc3_w);
    mlp_kernel<<<BATCH / 16, 256>>>(x, fc1_w, fc1_b, fc2_b, fc3_b, fcd_w, fcd_b);
    prep_osc_kernel<<<4, 256>>>(enc, obias, dec, fc4_w);
    osc_kernel<<<400, 256>>>();
    scan_kernel<<<BATCH / 256, 256>>>(x, fc4_b, out);
}

// round 13
// speedup vs baseline: 1.0463x; 1.0463x over previous
#include <cuda_runtime.h>
#include <cuda_bf16.h>
#include <math.h>

typedef unsigned long long u64;

#define N_OSC 50
#define N_PER 40
#define STEPS 100
#define BATCH 8192
#define NPAIR 25   // oscillator pairs; units = 25 ops x 128 bg64 = 3200 warps

// ---------------- packed f32x2 helpers ----------------
#define FMA2(d, a, b, c) \
    asm("fma.rn.f32x2 %0, %1, %2, %3;" : "=l"(d) : "l"(a), "l"(b), "l"(c))
#define PACK2(v, lo, hi) \
    asm("mov.b64 %0, {%1, %2};" : "=l"(v) : "f"(lo), "f"(hi))
#define UNPACK2(lo, hi, v) \
    asm("mov.b64 {%0, %1}, %2;" : "=f"(lo), "=f"(hi) : "l"(v))
#define RELU2(d, s)                      \
    do {                                 \
        float _lo, _hi;                  \
        UNPACK2(_lo, _hi, s);            \
        _lo = fmaxf(_lo, 0.f);           \
        _hi = fmaxf(_hi, 0.f);           \
        PACK2(d, _lo, _hi);              \
    } while (0)

// ---------------- device scratch (no allocs allowed) ----------------
__device__ float g_x3[BATCH * 100];            // o0 initial states, [b][100]
__device__ float g_direct[BATCH];              // direct torque (incl fcd_b)
__device__ float g_cpack[NPAIR * N_PER * 12];  // packed per-(osc-pair, n) consts
__device__ float2 g_fc2p[128 * 128];           // fc2_w k-major, duplicated pairs
__device__ float2 g_fc3p[128 * 128];           // fc3_w k-major, dup, zero-padded
__device__ float g_tqp[NPAIR * STEPS * BATCH]; // per-osc-pair torque partials

// ============================================================
// K0 (pos 1): prep_all — weight tables + oscillator constants
// ============================================================
__global__ void prep_all_kernel(const float* __restrict__ fc2_w,
                                const float* __restrict__ fc3_w,
                                const float* __restrict__ enc,
                                const float* __restrict__ obias,
                                const float* __restrict__ dec,
                                const float* __restrict__ fc4_w) {
    int i = blockIdx.x * blockDim.x + threadIdx.x;
    if (i < 16384) {
        int k = i / 128, j = i % 128;
        float w2 = fc2_w[j * 128 + k];
        g_fc2p[i] = make_float2(w2, w2);
        float w3 = (j < 100) ? fc3_w[j * 128 + k] : 0.f;
        g_fc3p[i] = make_float2(w3, w3);
    }
    if (i < NPAIR * N_PER) {
        int op = i / N_PER, n = i % N_PER;
        int oA = 2 * op, oB = 2 * op + 1;
        float* dst = g_cpack + (size_t)i * 12;
        dst[0]  = enc[oA * 80 + n * 2 + 0];
        dst[1]  = enc[oB * 80 + n * 2 + 0];
        dst[2]  = enc[oA * 80 + n * 2 + 1];
        dst[3]  = enc[oB * 80 + n * 2 + 1];
        dst[4]  = obias[oA * 40 + n];
        dst[5]  = obias[oB * 40 + n];
        dst[6]  = dec[oA * 80 + n];
        dst[7]  = dec[oB * 80 + n];
        dst[8]  = dec[oA * 80 + 40 + n];
        dst[9]  = dec[oB * 80 + 40 + n];
        dst[10] = fc4_w[oA * 40 + n];
        dst[11] = fc4_w[oB * 40 + n];
    }
}

// ============================================================
// K1 (pos 2): MLP v4 — 32 rows/block (256 blocks), 8 FFMA2 per LDG.
// thread (j = tid&127, rg = tid>>7) owns output j for rows
// 16rg..16rg+15 (8 row-pairs). s_h[k*16 + p] = h[k] rows (2p,2p+1).
// ============================================================
__global__ __launch_bounds__(256) void mlp_kernel(
    const float* __restrict__ x,
    const float* __restrict__ fc1_w, const float* __restrict__ fc1_b,
    const float* __restrict__ fc2_b, const float* __restrict__ fc3_b,
    const float* __restrict__ fcd_w, const float* __restrict__ fcd_b) {
    __shared__ u64 s_h[128 * 16];    // 16 KB
    __shared__ u64 s_h2[128 * 16];   // 16 KB

    const int tid = threadIdx.x;
    const int j = tid & 127;
    const int rg = tid >> 7;          // 0/1
    const int base = blockIdx.x * 32;
    const int r0 = base + 16 * rg;    // my 16 rows

    // ---- fc1: h[j] for my 8 row-pairs ----
    {
        float w0 = fc1_w[j * 2 + 0], w1 = fc1_w[j * 2 + 1], b1v = fc1_b[j];
        u64 w02, w12, b12;
        PACK2(w02, w0, w0);
        PACK2(w12, w1, w1);
        PACK2(b12, b1v, b1v);
#pragma unroll
        for (int p = 0; p < 8; ++p) {
            float2 ra = ((const float2*)x)[r0 + 2 * p];
            float2 rb = ((const float2*)x)[r0 + 2 * p + 1];
            u64 x0p, x1p, t;
            PACK2(x0p, ra.x, rb.x);
            PACK2(x1p, ra.y, rb.y);
            FMA2(t, w02, x0p, b12);
            FMA2(t, w12, x1p, t);
            RELU2(t, t);
            s_h[j * 16 + 8 * rg + p] = t;
        }
    }
    __syncthreads();

    // ---- fcd: direct term (warp 0, 32 rows, one per lane) ----
    if (tid < 32) {
        const float* shf = (const float*)s_h;   // shf[k*32 + r] = h[k] of row r
        float acc = 0.f;
#pragma unroll 8
        for (int k = 0; k < 128; ++k) acc = fmaf(shf[k * 32 + tid], fcd_w[k], acc);
        g_direct[base + tid] = acc + fcd_b[0];
    }

    // ---- fc2: 8 row-pair accumulators ----
    u64 a[8];
    {
        float bb = fc2_b[j];
        u64 b2;
        PACK2(b2, bb, bb);
#pragma unroll
        for (int p = 0; p < 8; ++p) a[p] = b2;
    }
    const u64* w2p = (const u64*)g_fc2p;
#pragma unroll 4
    for (int k = 0; k < 128; ++k) {
        u64 wp = __ldg(w2p + k * 128 + j);
        const u64* hh = s_h + k * 16 + 8 * rg;
#pragma unroll
        for (int p = 0; p < 8; ++p) FMA2(a[p], wp, hh[p], a[p]);
    }
#pragma unroll
    for (int p = 0; p < 8; ++p) {
        RELU2(a[p], a[p]);
        s_h2[j * 16 + 8 * rg + p] = a[p];
    }
    __syncthreads();

    // ---- fc3 ----
    u64 c[8];
    {
        float bb = (j < 100) ? fc3_b[j] : 0.f;
        u64 b2;
        PACK2(b2, bb, bb);
#pragma unroll
        for (int p = 0; p < 8; ++p) c[p] = b2;
    }
    const u64* w3p = (const u64*)g_fc3p;
#pragma unroll 4
    for (int k = 0; k < 128; ++k) {
        u64 wp = __ldg(w3p + k * 128 + j);
        const u64* hh = s_h2 + k * 16 + 8 * rg;
#pragma unroll
        for (int p = 0; p < 8; ++p) FMA2(c[p], wp, hh[p], c[p]);
    }
    if (j < 100) {
#pragma unroll
        for (int p = 0; p < 8; ++p) {
            float lo, hi;
            UNPACK2(lo, hi, c[p]);
            g_x3[(size_t)(r0 + 2 * p + 0) * 100 + j] = lo;
            g_x3[(size_t)(r0 + 2 * p + 1) * 100 + j] = hi;
        }
    }
}

// ============================================================
// K2 (pos 3): oscillator scan — R10 exact (best: 402us, at the
// FFMA2 rt=3 banking ceiling). 2-elem/thread, 400x256, prefetch.
// ============================================================
__global__ __launch_bounds__(256, 4) void osc_kernel() {
    __shared__ float4 s_c[120];  // one osc-pair slice: 40 n x 3 float4
    const unsigned op = blockIdx.x % NPAIR;
    if (threadIdx.x < 120)
        s_c[threadIdx.x] = ((const float4*)g_cpack)[op * 120 + threadIdx.x];
    __syncthreads();

    const int lane = threadIdx.x & 31;
    const int wrp = threadIdx.x >> 5;
    const unsigned bg = (blockIdx.x / NPAIR) * 8 + wrp;  // 128 groups of 64
    const int b0 = bg * 64 + lane;
    const int b1 = b0 + 32;

    u64 dt2;
    PACK2(dt2, 0.01f, 0.01f);

    float4 oA = __ldg((const float4*)(g_x3 + (size_t)b0 * 100 + op * 4));
    float4 oB = __ldg((const float4*)(g_x3 + (size_t)b1 * 100 + op * 4));
    u64 oxa, oya, oxb, oyb;
    PACK2(oxa, oA.x, oA.z);
    PACK2(oya, oA.y, oA.w);
    PACK2(oxb, oB.x, oB.z);
    PACK2(oyb, oB.y, oB.w);

    const ulonglong2* cp = (const ulonglong2*)s_c;
    float* tq_out = g_tqp + (size_t)op * (STEPS * BATCH) + b0;

    // prime the prefetch registers with n=0 constants
    ulonglong2 p0 = cp[0], p1 = cp[1], p2 = cp[2];

    for (int t = 0; t < STEPS; ++t) {
        u64 dxa = 0ull, dya = 0ull, tqa = 0ull;
        u64 dxb = 0ull, dyb = 0ull, tqb = 0ull;
#pragma unroll 4
        for (int n = 0; n < N_PER; ++n) {
            ulonglong2 c0 = p0, c1 = p1, c2 = p2;
            const int m = (n == N_PER - 1) ? 0 : (n + 1) * 3;
            p0 = cp[m];
            p1 = cp[m + 1];
            p2 = cp[m + 2];

            u64 ta, tb, aa, ab;
            FMA2(ta, oxa, c0.x, c1.x);
            FMA2(tb, oxb, c0.x, c1.x);
            FMA2(ta, oya, c0.y, ta);
            FMA2(tb, oyb, c0.y, tb);
            RELU2(aa, ta);
            RELU2(ab, tb);
            FMA2(dxa, c1.y, aa, dxa);
            FMA2(dxb, c1.y, ab, dxb);
            FMA2(dya, c2.x, aa, dya);
            FMA2(dyb, c2.x, ab, dyb);
            FMA2(tqa, c2.y, aa, tqa);
            FMA2(tqb, c2.y, ab, tqb);
        }
        FMA2(oxa, dt2, dxa, oxa);
        FMA2(oya, dt2, dya, oya);
        FMA2(oxb, dt2, dxb, oxb);
        FMA2(oyb, dt2, dyb, oyb);
        float sl, sh;
        UNPACK2(sl, sh, tqa);
        float s0 = sl + sh;
        UNPACK2(sl, sh, tqb);
        float s1 = sl + sh;
        tq_out[t * BATCH]      = s0;
        tq_out[t * BATCH + 32] = s1;
    }
}

// ============================================================
// K3 (pos 4 — PROFILED): fused reduce + pendulum scan + outputs
// ============================================================
__global__ void scan_kernel(const float* __restrict__ x,
                            const float* __restrict__ fc4_b,
                            float* __restrict__ out) {
    int b = blockIdx.x * blockDim.x + threadIdx.x;  // < BATCH
    float theta = x[b * 2 + 0];
    float omega = 0.f;
    const float dir = g_direct[b] + fc4_b[0];
    float2* outL = (float2*)out;
    float* outT = out + STEPS * BATCH * 2;
    for (int t = 0; t < STEPS; ++t) {
        float s = 0.f;
        const float* p = g_tqp + (size_t)t * BATCH + b;
#pragma unroll
        for (int q = 0; q < NPAIR; ++q) s += p[(size_t)q * (STEPS * BATCH)];
        float tau = s + dir;
        float alpha = tau - sinf(theta) - 0.1f * omega;
        float th2 = theta + 0.01f * omega;
        float om2 = omega + 0.01f * alpha;
        outL[t * BATCH + b] = make_float2(th2, om2);
        outT[t * BATCH + b] = tau;
        theta = th2;
        omega = om2;
    }
}

// ============================================================
extern "C" void kernel_launch(void* const* d_in, const int* in_sizes, int n_in,
                              void* d_out, int out_size) {
    const float* x     = (const float*)d_in[0];
    const float* fc1_w = (const float*)d_in[1];
    const float* fc1_b = (const float*)d_in[2];
    const float* fc2_w = (const float*)d_in[3];
    const float* fc2_b = (const float*)d_in[4];
    const float* fc3_w = (const float*)d_in[5];
    const float* fc3_b = (const float*)d_in[6];
    const float* fcd_w = (const float*)d_in[7];
    const float* fcd_b = (const float*)d_in[8];
    const float* enc   = (const float*)d_in[9];
    const float* obias = (const float*)d_in[10];
    const float* dec   = (const float*)d_in[11];
    const float* fc4_w = (const float*)d_in[12];
    const float* fc4_b = (const float*)d_in[13];
    float* out = (float*)d_out;

    prep_all_kernel<<<64, 256>>>(fc2_w, fc3_w, enc, obias, dec, fc4_w);
    mlp_kernel<<<BATCH / 32, 256>>>(x, fc1_w, fc1_b, fc2_b, fc3_b, fcd_w, fcd_b);
    osc_kernel<<<400, 256>>>();
    scan_kernel<<<BATCH / 256, 256>>>(x, fc4_b, out);
}

// round 17
// speedup vs baseline: 1.2746x; 1.2182x over previous
// Net_22067541967436 - R16 submission.
// THEORY (carried from R13, untested due to two format failures):
//   R13 profiling showed scan_kernel at 141.8us: the 82MB g_tqp reduction
//   was fused into an 8192-thread scan (DRAM 7.7%, 606 GB/s, occ 12%).
//   Fix: standalone reduce_kernel with 819K threads (STEPS*BATCH) sums the
//   25 per-osc-pair partials, adds g_direct + fc4_b, and writes the FINAL
//   torque directly into the output buffer (86MB at ~5TB/s => ~20us, as
//   measured for the standalone reduce in early rounds). scan_kernel then
//   only reads 3.2MB of torques and stores 8.2MB of l_states (~15-25us).
// PREDICTION: scan path 142us -> ~40us, total 571 -> ~455-480us.
//   Profiled position-4 kernel (reduce) should show DRAM busy >= 55%.
// Budget: osc 402us (at FFMA2 rt=3 register-banking ceiling),
//   prep+mlp ~27us, reduce+scan ~40us.

#include <cuda_runtime.h>
#include <cuda_bf16.h>
#include <math.h>

typedef unsigned long long u64;

#define N_OSC 50
#define N_PER 40
#define STEPS 100
#define BATCH 8192
#define NPAIR 25

#define FMA2(d, a, b, c) \
    asm("fma.rn.f32x2 %0, %1, %2, %3;" : "=l"(d) : "l"(a), "l"(b), "l"(c))
#define PACK2(v, lo, hi) \
    asm("mov.b64 %0, {%1, %2};" : "=l"(v) : "f"(lo), "f"(hi))
#define UNPACK2(lo, hi, v) \
    asm("mov.b64 {%0, %1}, %2;" : "=f"(lo), "=f"(hi) : "l"(v))
#define RELU2(d, s)                      \
    do {                                 \
        float _lo, _hi;                  \
        UNPACK2(_lo, _hi, s);            \
        _lo = fmaxf(_lo, 0.f);           \
        _hi = fmaxf(_hi, 0.f);           \
        PACK2(d, _lo, _hi);              \
    } while (0)

__device__ float g_x3[BATCH * 100];
__device__ float g_direct[BATCH];
__device__ float g_cpack[NPAIR * N_PER * 12];
__device__ float2 g_fc2p[128 * 128];
__device__ float2 g_fc3p[128 * 128];
__device__ float g_tqp[NPAIR * STEPS * BATCH];

// K0 (pos 1): prep weight tables + oscillator constants
__global__ void prep_all_kernel(const float* __restrict__ fc2_w,
                                const float* __restrict__ fc3_w,
                                const float* __restrict__ enc,
                                const float* __restrict__ obias,
                                const float* __restrict__ dec,
                                const float* __restrict__ fc4_w) {
    int i = blockIdx.x * blockDim.x + threadIdx.x;
    if (i < 16384) {
        int k = i / 128, j = i % 128;
        float w2 = fc2_w[j * 128 + k];
        g_fc2p[i] = make_float2(w2, w2);
        float w3 = (j < 100) ? fc3_w[j * 128 + k] : 0.f;
        g_fc3p[i] = make_float2(w3, w3);
    }
    if (i < NPAIR * N_PER) {
        int op = i / N_PER, n = i % N_PER;
        int oA = 2 * op, oB = 2 * op + 1;
        float* dst = g_cpack + (size_t)i * 12;
        dst[0]  = enc[oA * 80 + n * 2 + 0];
        dst[1]  = enc[oB * 80 + n * 2 + 0];
        dst[2]  = enc[oA * 80 + n * 2 + 1];
        dst[3]  = enc[oB * 80 + n * 2 + 1];
        dst[4]  = obias[oA * 40 + n];
        dst[5]  = obias[oB * 40 + n];
        dst[6]  = dec[oA * 80 + n];
        dst[7]  = dec[oB * 80 + n];
        dst[8]  = dec[oA * 80 + 40 + n];
        dst[9]  = dec[oB * 80 + 40 + n];
        dst[10] = fc4_w[oA * 40 + n];
        dst[11] = fc4_w[oB * 40 + n];
    }
}

// K1 (pos 2): MLP, 32 rows/block, 8 FFMA2 per weight LDG
__global__ __launch_bounds__(256) void mlp_kernel(
    const float* __restrict__ x,
    const float* __restrict__ fc1_w, const float* __restrict__ fc1_b,
    const float* __restrict__ fc2_b, const float* __restrict__ fc3_b,
    const float* __restrict__ fcd_w, const float* __restrict__ fcd_b) {
    __shared__ u64 s_h[128 * 16];
    __shared__ u64 s_h2[128 * 16];

    const int tid = threadIdx.x;
    const int j = tid & 127;
    const int rg = tid >> 7;
    const int base = blockIdx.x * 32;
    const int r0 = base + 16 * rg;

    {
        float w0 = fc1_w[j * 2 + 0], w1 = fc1_w[j * 2 + 1], b1v = fc1_b[j];
        u64 w02, w12, b12;
        PACK2(w02, w0, w0);
        PACK2(w12, w1, w1);
        PACK2(b12, b1v, b1v);
#pragma unroll
        for (int p = 0; p < 8; ++p) {
            float2 ra = ((const float2*)x)[r0 + 2 * p];
            float2 rb = ((const float2*)x)[r0 + 2 * p + 1];
            u64 x0p, x1p, t;
            PACK2(x0p, ra.x, rb.x);
            PACK2(x1p, ra.y, rb.y);
            FMA2(t, w02, x0p, b12);
            FMA2(t, w12, x1p, t);
            RELU2(t, t);
            s_h[j * 16 + 8 * rg + p] = t;
        }
    }
    __syncthreads();

    if (tid < 32) {
        const float* shf = (const float*)s_h;
        float acc = 0.f;
#pragma unroll 8
        for (int k = 0; k < 128; ++k) acc = fmaf(shf[k * 32 + tid], fcd_w[k], acc);
        g_direct[base + tid] = acc + fcd_b[0];
    }

    u64 a[8];
    {
        float bb = fc2_b[j];
        u64 b2;
        PACK2(b2, bb, bb);
#pragma unroll
        for (int p = 0; p < 8; ++p) a[p] = b2;
    }
    const u64* w2p = (const u64*)g_fc2p;
#pragma unroll 4
    for (int k = 0; k < 128; ++k) {
        u64 wp = __ldg(w2p + k * 128 + j);
        const u64* hh = s_h + k * 16 + 8 * rg;
#pragma unroll
        for (int p = 0; p < 8; ++p) FMA2(a[p], wp, hh[p], a[p]);
    }
#pragma unroll
    for (int p = 0; p < 8; ++p) {
        RELU2(a[p], a[p]);
        s_h2[j * 16 + 8 * rg + p] = a[p];
    }
    __syncthreads();

    u64 c[8];
    {
        float bb = (j < 100) ? fc3_b[j] : 0.f;
        u64 b2;
        PACK2(b2, bb, bb);
#pragma unroll
        for (int p = 0; p < 8; ++p) c[p] = b2;
    }
    const u64* w3p = (const u64*)g_fc3p;
#pragma unroll 4
    for (int k = 0; k < 128; ++k) {
        u64 wp = __ldg(w3p + k * 128 + j);
        const u64* hh = s_h2 + k * 16 + 8 * rg;
#pragma unroll
        for (int p = 0; p < 8; ++p) FMA2(c[p], wp, hh[p], c[p]);
    }
    if (j < 100) {
#pragma unroll
        for (int p = 0; p < 8; ++p) {
            float lo, hi;
            UNPACK2(lo, hi, c[p]);
            g_x3[(size_t)(r0 + 2 * p + 0) * 100 + j] = lo;
            g_x3[(size_t)(r0 + 2 * p + 1) * 100 + j] = hi;
        }
    }
}

// K2 (pos 3): oscillator scan (best measured config: 402us)
__global__ __launch_bounds__(256, 4) void osc_kernel() {
    __shared__ float4 s_c[120];
    const unsigned op = blockIdx.x % NPAIR;
    if (threadIdx.x < 120)
        s_c[threadIdx.x] = ((const float4*)g_cpack)[op * 120 + threadIdx.x];
    __syncthreads();

    const int lane = threadIdx.x & 31;
    const int wrp = threadIdx.x >> 5;
    const unsigned bg = (blockIdx.x / NPAIR) * 8 + wrp;
    const int b0 = bg * 64 + lane;
    const int b1 = b0 + 32;

    u64 dt2;
    PACK2(dt2, 0.01f, 0.01f);

    float4 oA = __ldg((const float4*)(g_x3 + (size_t)b0 * 100 + op * 4));
    float4 oB = __ldg((const float4*)(g_x3 + (size_t)b1 * 100 + op * 4));
    u64 oxa, oya, oxb, oyb;
    PACK2(oxa, oA.x, oA.z);
    PACK2(oya, oA.y, oA.w);
    PACK2(oxb, oB.x, oB.z);
    PACK2(oyb, oB.y, oB.w);

    const ulonglong2* cp = (const ulonglong2*)s_c;
    float* tq_out = g_tqp + (size_t)op * (STEPS * BATCH) + b0;

    ulonglong2 p0 = cp[0], p1 = cp[1], p2 = cp[2];

    for (int t = 0; t < STEPS; ++t) {
        u64 dxa = 0ull, dya = 0ull, tqa = 0ull;
        u64 dxb = 0ull, dyb = 0ull, tqb = 0ull;
#pragma unroll 4
        for (int n = 0; n < N_PER; ++n) {
            ulonglong2 c0 = p0, c1 = p1, c2 = p2;
            const int m = (n == N_PER - 1) ? 0 : (n + 1) * 3;
            p0 = cp[m];
            p1 = cp[m + 1];
            p2 = cp[m + 2];

            u64 ta, tb, aa, ab;
            FMA2(ta, oxa, c0.x, c1.x);
            FMA2(tb, oxb, c0.x, c1.x);
            FMA2(ta, oya, c0.y, ta);
            FMA2(tb, oyb, c0.y, tb);
            RELU2(aa, ta);
            RELU2(ab, tb);
            FMA2(dxa, c1.y, aa, dxa);
            FMA2(dxb, c1.y, ab, dxb);
            FMA2(dya, c2.x, aa, dya);
            FMA2(dyb, c2.x, ab, dyb);
            FMA2(tqa, c2.y, aa, tqa);
            FMA2(tqb, c2.y, ab, tqb);
        }
        FMA2(oxa, dt2, dxa, oxa);
        FMA2(oya, dt2, dya, oya);
        FMA2(oxb, dt2, dxb, oxb);
        FMA2(oyb, dt2, dyb, oyb);
        float sl, sh;
        UNPACK2(sl, sh, tqa);
        float s0 = sl + sh;
        UNPACK2(sl, sh, tqb);
        float s1 = sl + sh;
        tq_out[t * BATCH]      = s0;
        tq_out[t * BATCH + 32] = s1;
    }
}

// K3 (pos 4, profiled): reduce 25 partials -> final torque in out
__global__ void reduce_kernel(const float* __restrict__ fc4_b,
                              float* __restrict__ out) {
    int i = blockIdx.x * blockDim.x + threadIdx.x;
    float s = 0.f;
#pragma unroll
    for (int q = 0; q < NPAIR; ++q) s += g_tqp[(size_t)q * (STEPS * BATCH) + i];
    out[STEPS * BATCH * 2 + i] = s + g_direct[i & (BATCH - 1)] + fc4_b[0];
}

// K4 (pos 5): pendulum scan, reads final torques, writes l_states
__global__ void scan_kernel(const float* __restrict__ x,
                            float* __restrict__ out) {
    int b = blockIdx.x * blockDim.x + threadIdx.x;
    float theta = x[b * 2 + 0];
    float omega = 0.f;
    float2* outL = (float2*)out;
    const float* tq = out + STEPS * BATCH * 2;
#pragma unroll 4
    for (int t = 0; t < STEPS; ++t) {
        float tau = __ldg(tq + t * BATCH + b);
        float alpha = tau - sinf(theta) - 0.1f * omega;
        float th2 = theta + 0.01f * omega;
        float om2 = omega + 0.01f * alpha;
        outL[t * BATCH + b] = make_float2(th2, om2);
        theta = th2;
        omega = om2;
    }
}

extern "C" void kernel_launch(void* const* d_in, const int* in_sizes, int n_in,
                              void* d_out, int out_size) {
    const float* x     = (const float*)d_in[0];
    const float* fc1_w = (const float*)d_in[1];
    const float* fc1_b = (const float*)d_in[2];
    const float* fc2_w = (const float*)d_in[3];
    const float* fc2_b = (const float*)d_in[4];
    const float* fc3_w = (const float*)d_in[5];
    const float* fc3_b = (const float*)d_in[6];
    const float* fcd_w = (const float*)d_in[7];
    const float* fcd_b = (const float*)d_in[8];
    const float* enc   = (const float*)d_in[9];
    const float* obias = (const float*)d_in[10];
    const float* dec   = (const float*)d_in[11];
    const float* fc4_w = (const float*)d_in[12];
    const float* fc4_b = (const float*)d_in[13];
    float* out = (float*)d_out;

    prep_all_kernel<<<64, 256>>>(fc2_w, fc3_w, enc, obias, dec, fc4_w);
    mlp_kernel<<<BATCH / 32, 256>>>(x, fc1_w, fc1_b, fc2_b, fc3_b, fcd_w, fcd_b);
    osc_kernel<<<400, 256>>>();
    reduce_kernel<<<(STEPS * BATCH) / 256, 256>>>(fc4_b, out);
    scan_kernel<<<BATCH / 256, 256>>>(x, out);
}